// round 2
// baseline (speedup 1.0000x reference)
#include <cuda_runtime.h>
#include <cstdint>

#define NDIM 768
#define NN   (768*768)        // 589824 rows
#define DD   128

// ---------------- scratch (device globals; no allocation in kernel_launch) ----
__device__ float g_xn[(size_t)NN * 128];   // tf32-rounded LN(x), [r][d]
__device__ float g_A [(size_t)128 * NN];   // a transposed: [d][i*768+k]
__device__ float g_B [(size_t)128 * NN];   // b transposed: [d][j*768+k]
__device__ float g_T [(size_t)128 * NN];   // t transposed: [d][i*768+j]
__device__ float g_Wc[512 * 128];          // interleaved (g,p) projection weights, tf32
__device__ float g_Gw[128 * 128];          // g_out_w tf32
__device__ float g_Pw[128 * 128];          // p_out_w tf32

// ---------------- helpers ----------------------------------------------------
__device__ __forceinline__ float tf32r(float x) {
    unsigned u;
    asm("cvt.rna.tf32.f32 %0, %1;" : "=r"(u) : "f"(x));
    return __uint_as_float(u);
}

__device__ __forceinline__ void mma8(float c[4], const unsigned a[4], const unsigned b[2]) {
    asm volatile(
        "mma.sync.aligned.m16n8k8.row.col.f32.tf32.tf32.f32 "
        "{%0,%1,%2,%3},{%4,%5,%6,%7},{%8,%9},{%0,%1,%2,%3};"
        : "+f"(c[0]), "+f"(c[1]), "+f"(c[2]), "+f"(c[3])
        : "r"(a[0]), "r"(a[1]), "r"(a[2]), "r"(a[3]), "r"(b[0]), "r"(b[1]));
}

// 128x128x128 warp-tiled compute. sA: [128][132] rows=m cols=k. sB: [128][132] rows=n cols=k.
// warps 2x4 (m x n), warp tile 64x32. Padding 4 floats -> all fragment LDS conflict-free.
__device__ __forceinline__ void gemm_128(const float* sA, const float* sB,
                                         float acc[4][4][4],
                                         int wm, int wn, int qr, int qc) {
    for (int k = 0; k < 128; k += 8) {
        unsigned af[4][4], bf[4][2];
#pragma unroll
        for (int mt = 0; mt < 4; mt++) {
            const float* p = sA + (wm + mt * 16 + qr) * 132 + k + qc;
            af[mt][0] = __float_as_uint(p[0]);
            af[mt][1] = __float_as_uint(p[8 * 132]);
            af[mt][2] = __float_as_uint(p[4]);
            af[mt][3] = __float_as_uint(p[8 * 132 + 4]);
        }
#pragma unroll
        for (int nt = 0; nt < 4; nt++) {
            const float* p = sB + (wn + nt * 8 + qr) * 132 + k + qc;
            bf[nt][0] = __float_as_uint(p[0]);
            bf[nt][1] = __float_as_uint(p[4]);
        }
#pragma unroll
        for (int mt = 0; mt < 4; mt++)
#pragma unroll
            for (int nt = 0; nt < 4; nt++)
                mma8(acc[mt][nt], af[mt], bf[nt]);
    }
}

// Same but A operand stored transposed in smem: sT[k][132] rows=k cols=m.
__device__ __forceinline__ void gemm_128_At(const float* sT, const float* sB,
                                            float acc[4][4][4],
                                            int wm, int wn, int qr, int qc) {
    for (int k = 0; k < 128; k += 8) {
        unsigned af[4][4], bf[4][2];
#pragma unroll
        for (int mt = 0; mt < 4; mt++) {
            int r = wm + mt * 16 + qr;
            const float* p0 = sT + (k + qc) * 132 + r;
            const float* p1 = sT + (k + qc + 4) * 132 + r;
            af[mt][0] = __float_as_uint(p0[0]);
            af[mt][1] = __float_as_uint(p0[8]);
            af[mt][2] = __float_as_uint(p1[0]);
            af[mt][3] = __float_as_uint(p1[8]);
        }
#pragma unroll
        for (int nt = 0; nt < 4; nt++) {
            const float* p = sB + (wn + nt * 8 + qr) * 132 + k + qc;
            bf[nt][0] = __float_as_uint(p[0]);
            bf[nt][1] = __float_as_uint(p[4]);
        }
#pragma unroll
        for (int mt = 0; mt < 4; mt++)
#pragma unroll
            for (int nt = 0; nt < 4; nt++)
                mma8(acc[mt][nt], af[mt], bf[nt]);
    }
}

// ---------------- kernel 0: weight prep --------------------------------------
// Wc[2e][d] = g_in_w[e][d], Wc[2e+1][d] = p_in_w[e][d]  (tf32-rounded).
__global__ void prep_w_kernel(const float* __restrict__ gin, const float* __restrict__ pin,
                              const float* __restrict__ gout, const float* __restrict__ pout) {
    int stride = gridDim.x * blockDim.x;
    for (int idx = blockIdx.x * blockDim.x + threadIdx.x; idx < 256 * 128; idx += stride) {
        int e = idx >> 7, d = idx & 127;
        g_Wc[(2 * e) * 128 + d]     = tf32r(gin[idx]);
        g_Wc[(2 * e + 1) * 128 + d] = tf32r(pin[idx]);
    }
    for (int idx = blockIdx.x * blockDim.x + threadIdx.x; idx < 128 * 128; idx += stride) {
        g_Gw[idx] = tf32r(gout[idx]);
        g_Pw[idx] = tf32r(pout[idx]);
    }
}

// ---------------- kernel 1: LayerNorm(x) -> g_xn (tf32-rounded fp32) ---------
__global__ void __launch_bounds__(256) ln_in_kernel(const float* __restrict__ x,
                                                    const float* __restrict__ w,
                                                    const float* __restrict__ b) {
    int warp = threadIdx.x >> 5, lane = threadIdx.x & 31;
    size_t r = (size_t)blockIdx.x * 8 + warp;
    const float4 xv = ((const float4*)(x + r * 128))[lane];
    float s  = xv.x + xv.y + xv.z + xv.w;
    float s2 = xv.x * xv.x + xv.y * xv.y + xv.z * xv.z + xv.w * xv.w;
#pragma unroll
    for (int o = 16; o > 0; o >>= 1) {
        s  += __shfl_xor_sync(0xffffffffu, s,  o);
        s2 += __shfl_xor_sync(0xffffffffu, s2, o);
    }
    float m   = s * (1.0f / 128.0f);
    float var = s2 * (1.0f / 128.0f) - m * m;
    float inv = rsqrtf(var + 1e-5f);
    float4 wv = ((const float4*)w)[lane];
    float4 bv = ((const float4*)b)[lane];
    float4 o4;
    o4.x = tf32r((xv.x - m) * inv * wv.x + bv.x);
    o4.y = tf32r((xv.y - m) * inv * wv.y + bv.y);
    o4.z = tf32r((xv.z - m) * inv * wv.z + bv.z);
    o4.w = tf32r((xv.w - m) * inv * wv.w + bv.w);
    ((float4*)(g_xn + r * 128))[lane] = o4;
}

// ---------------- kernel 2: projections + gate + mask, transposed store ------
// C[r][n] = xn[r] . Wc[n],  n in [ntile*128, +128).  Channel ch = n/2: g at even n, p at odd n.
// gp = sigmoid(g)*p; ch<128 -> a_t[ch][i][k]*mask ; else b_t[ch-128][i][k].
__global__ void __launch_bounds__(256) proj_kernel(const float* __restrict__ mask) {
    extern __shared__ float sm[];
    float* sA  = sm;                 // 128*132
    float* sW  = sm + 16896;         // 128*132
    float* msk = sm + 2 * 16896;     // 128
    int ntile = blockIdx.x;
    int rt = blockIdx.y;
    int i = rt / 6, k0 = (rt % 6) * 128;
    int tid = threadIdx.x;

    if (tid < 128) msk[tid] = mask[i * 768 + k0 + tid];

    const float4* Ag = (const float4*)(g_xn + (size_t)(i * 768 + k0) * 128);
    const float4* Wg = (const float4*)(g_Wc + (size_t)ntile * 128 * 128);
#pragma unroll
    for (int it = 0; it < 16; it++) {
        int idx = it * 256 + tid;
        int r = idx >> 5, c4 = idx & 31;
        *(float4*)&sA[r * 132 + c4 * 4] = Ag[(size_t)r * 32 + c4];
        *(float4*)&sW[r * 132 + c4 * 4] = Wg[(size_t)r * 32 + c4];
    }
    __syncthreads();

    int warp = tid >> 5, lane = tid & 31;
    int wm = (warp >> 2) * 64, wn = (warp & 3) * 32;
    int qr = lane >> 2, qc = lane & 3;
    float acc[4][4][4];
#pragma unroll
    for (int a = 0; a < 4; a++)
#pragma unroll
        for (int b = 0; b < 4; b++)
#pragma unroll
            for (int c = 0; c < 4; c++) acc[a][b][c] = 0.0f;

    gemm_128(sA, sW, acc, wm, wn, qr, qc);
    __syncthreads();          // done reading sA -> reuse as staging

    float* stg = sA;          // [64 ch][132]
    bool isA = (ntile < 2);
#pragma unroll
    for (int mt = 0; mt < 4; mt++)
#pragma unroll
        for (int nt = 0; nt < 4; nt++) {
            int rm0 = wm + mt * 16 + qr, rm1 = rm0 + 8;
            int chl = (wn >> 1) + nt * 4 + qc;
            float v0 = acc[mt][nt][1] * (1.0f / (1.0f + __expf(-acc[mt][nt][0])));
            float v1 = acc[mt][nt][3] * (1.0f / (1.0f + __expf(-acc[mt][nt][2])));
            if (isA) { v0 *= msk[rm0]; v1 *= msk[rm1]; }
            stg[chl * 132 + rm0] = tf32r(v0);
            stg[chl * 132 + rm1] = tf32r(v1);
        }
    __syncthreads();

#pragma unroll
    for (int it = 0; it < 8; it++) {
        int idx = it * 256 + tid;              // 0..2047 float4s
        int chl = idx >> 5, k4 = idx & 31;
        float4 v = *(float4*)&stg[chl * 132 + k4 * 4];
        int ch = ntile * 64 + chl;
        float* dst = (ch < 128) ? (g_A + (size_t)ch * NN) : (g_B + (size_t)(ch - 128) * NN);
        *(float4*)&dst[i * 768 + k0 + k4 * 4] = v;
    }
}

// ---------------- kernel 3: batched einsum  t_d = A_d @ B_d^T ----------------
__global__ void __launch_bounds__(256) bgemm_kernel() {
    extern __shared__ float sm[];
    float* sA = sm;
    float* sB = sm + 16896;
    int jt = blockIdx.x, it = blockIdx.y, d = blockIdx.z;
    int tid = threadIdx.x;
    const float* Abase = g_A + (size_t)d * NN + (size_t)it * 128 * 768;
    const float* Bbase = g_B + (size_t)d * NN + (size_t)jt * 128 * 768;

    int warp = tid >> 5, lane = tid & 31;
    int wm = (warp >> 2) * 64, wn = (warp & 3) * 32;
    int qr = lane >> 2, qc = lane & 3;
    float acc[4][4][4];
#pragma unroll
    for (int a = 0; a < 4; a++)
#pragma unroll
        for (int b = 0; b < 4; b++)
#pragma unroll
            for (int c = 0; c < 4; c++) acc[a][b][c] = 0.0f;

    for (int kc = 0; kc < 768; kc += 128) {
        __syncthreads();
#pragma unroll
        for (int itld = 0; itld < 16; itld++) {
            int idx = itld * 256 + tid;
            int r = idx >> 5, c4 = idx & 31;
            *(float4*)&sA[r * 132 + c4 * 4] = *(const float4*)&Abase[(size_t)r * 768 + kc + c4 * 4];
            *(float4*)&sB[r * 132 + c4 * 4] = *(const float4*)&Bbase[(size_t)r * 768 + kc + c4 * 4];
        }
        __syncthreads();
        gemm_128(sA, sB, acc, wm, wn, qr, qc);
    }

    float* out = g_T + (size_t)d * NN;
#pragma unroll
    for (int mt = 0; mt < 4; mt++)
#pragma unroll
        for (int nt = 0; nt < 4; nt++) {
            int rm0 = it * 128 + wm + mt * 16 + qr;
            int cn  = jt * 128 + wn + nt * 8 + qc * 2;
            *(float2*)&out[(size_t)rm0 * 768 + cn]       = make_float2(acc[mt][nt][0], acc[mt][nt][1]);
            *(float2*)&out[(size_t)(rm0 + 8) * 768 + cn] = make_float2(acc[mt][nt][2], acc[mt][nt][3]);
        }
}

// ---------------- kernel 4: LN(t) over d + gated output projection -----------
__global__ void __launch_bounds__(256) final_kernel(const float* __restrict__ now_w,
                                                    const float* __restrict__ now_b,
                                                    float* __restrict__ out) {
    extern __shared__ float sm[];
    float* sX    = sm;                 // xn tile [j][d]
    float* sT    = sm + 16896;         // t tile  [d][j]
    float* sW    = sm + 2 * 16896;     // weights [e][d]
    float* meanv = sm + 3 * 16896;     // 128
    float* invv  = meanv + 128;        // 128
    int rt = blockIdx.x;
    int i = rt / 6, j0 = (rt % 6) * 128;
    int tid = threadIdx.x;

    const float4* Xg = (const float4*)(g_xn + (size_t)(i * 768 + j0) * 128);
    const float*  Tg = g_T + (size_t)i * 768 + j0;
    const float4* Gg = (const float4*)g_Gw;
#pragma unroll
    for (int it = 0; it < 16; it++) {
        int idx = it * 256 + tid;
        int r = idx >> 5, c4 = idx & 31;
        *(float4*)&sX[r * 132 + c4 * 4] = Xg[(size_t)r * 32 + c4];
        *(float4*)&sT[r * 132 + c4 * 4] = *(const float4*)&Tg[(size_t)r * NN + c4 * 4]; // r=d, c4*4=j
        *(float4*)&sW[r * 132 + c4 * 4] = Gg[(size_t)r * 32 + c4];
    }
    __syncthreads();

    // LN stats over d for each column j (2 threads per column)
    {
        int j = tid >> 1, h = tid & 1;
        float s = 0.0f, s2 = 0.0f;
        for (int dd = h * 64; dd < h * 64 + 64; dd++) {
            float v = sT[dd * 132 + j];
            s += v; s2 += v * v;
        }
        s  += __shfl_xor_sync(0xffffffffu, s,  1);
        s2 += __shfl_xor_sync(0xffffffffu, s2, 1);
        if (h == 0) {
            float m   = s * (1.0f / 128.0f);
            float var = s2 * (1.0f / 128.0f) - m * m;
            meanv[j] = m;
            invv[j]  = rsqrtf(var + 1e-5f);
        }
    }
    __syncthreads();

    // normalize t in place (tf32-rounded)
    for (int it = 0; it < 64; it++) {
        int idx = it * 256 + tid;          // 0..16383
        int dd = idx >> 7, j = idx & 127;
        float v = sT[dd * 132 + j];
        v = (v - meanv[j]) * invv[j] * now_w[dd] + now_b[dd];
        sT[dd * 132 + j] = tf32r(v);
    }
    __syncthreads();

    int warp = tid >> 5, lane = tid & 31;
    int wm = (warp >> 2) * 64, wn = (warp & 3) * 32;
    int qr = lane >> 2, qc = lane & 3;

    // GEMM 1: gate = sigmoid(xn @ g_out_w^T)
    float sig[4][4][4];
#pragma unroll
    for (int a = 0; a < 4; a++)
#pragma unroll
        for (int b = 0; b < 4; b++)
#pragma unroll
            for (int c = 0; c < 4; c++) sig[a][b][c] = 0.0f;
    gemm_128(sX, sW, sig, wm, wn, qr, qc);
#pragma unroll
    for (int a = 0; a < 4; a++)
#pragma unroll
        for (int b = 0; b < 4; b++)
#pragma unroll
            for (int c = 0; c < 4; c++)
                sig[a][b][c] = 1.0f / (1.0f + __expf(-sig[a][b][c]));
    __syncthreads();

    // reload weights = p_out_w
    const float4* Pg = (const float4*)g_Pw;
#pragma unroll
    for (int it = 0; it < 16; it++) {
        int idx = it * 256 + tid;
        int r = idx >> 5, c4 = idx & 31;
        *(float4*)&sW[r * 132 + c4 * 4] = Pg[(size_t)r * 32 + c4];
    }
    __syncthreads();

    // GEMM 2: p_out = LN(t) @ p_out_w^T   (A stored transposed [d][j])
    float acc[4][4][4];
#pragma unroll
    for (int a = 0; a < 4; a++)
#pragma unroll
        for (int b = 0; b < 4; b++)
#pragma unroll
            for (int c = 0; c < 4; c++) acc[a][b][c] = 0.0f;
    gemm_128_At(sT, sW, acc, wm, wn, qr, qc);

#pragma unroll
    for (int mt = 0; mt < 4; mt++)
#pragma unroll
        for (int nt = 0; nt < 4; nt++) {
            int rj = wm + mt * 16 + qr;
            int cn = wn + nt * 8 + qc * 2;
            size_t b0 = (size_t)(i * 768 + j0 + rj) * 128 + cn;
            size_t b1 = (size_t)(i * 768 + j0 + rj + 8) * 128 + cn;
            *(float2*)&out[b0] = make_float2(sig[mt][nt][0] * acc[mt][nt][0],
                                             sig[mt][nt][1] * acc[mt][nt][1]);
            *(float2*)&out[b1] = make_float2(sig[mt][nt][2] * acc[mt][nt][2],
                                             sig[mt][nt][3] * acc[mt][nt][3]);
        }
}

// ---------------- launch ------------------------------------------------------
extern "C" void kernel_launch(void* const* d_in, const int* in_sizes, int n_in,
                              void* d_out, int out_size) {
    const float* x    = (const float*)d_in[0];
    const float* mask = (const float*)d_in[1];
    const float* niw  = (const float*)d_in[2];
    const float* nib  = (const float*)d_in[3];
    const float* giw  = (const float*)d_in[4];
    const float* piw  = (const float*)d_in[5];
    const float* now  = (const float*)d_in[6];
    const float* nob  = (const float*)d_in[7];
    const float* gow  = (const float*)d_in[8];
    const float* pwo  = (const float*)d_in[9];
    float* out = (float*)d_out;

    size_t sm2 = (size_t)2 * 16896 * 4 + 512;            // proj: 135680 B
    size_t sm3 = (size_t)2 * 16896 * 4;                  // bgemm: 135168 B
    size_t sm4 = (size_t)3 * 16896 * 4 + 256 * 4;        // final: 203776 B
    cudaFuncSetAttribute(proj_kernel,  cudaFuncAttributeMaxDynamicSharedMemorySize, (int)sm2);
    cudaFuncSetAttribute(bgemm_kernel, cudaFuncAttributeMaxDynamicSharedMemorySize, (int)sm3);
    cudaFuncSetAttribute(final_kernel, cudaFuncAttributeMaxDynamicSharedMemorySize, (int)sm4);

    prep_w_kernel<<<64, 256>>>(giw, piw, gow, pwo);
    ln_in_kernel<<<NN / 8, 256>>>(x, niw, nib);
    proj_kernel<<<dim3(4, 4608), 256, sm2>>>(mask);
    bgemm_kernel<<<dim3(6, 6, 128), 256, sm3>>>();
    final_kernel<<<4608, 256, sm4>>>(now, nob, out);
}

// round 3
// speedup vs baseline: 1.4583x; 1.4583x over previous
#include <cuda_runtime.h>
#include <cstdint>

#define NN (768*768)

// ---------------- scratch -----------------------------------------------------
__device__ float g_xn[(size_t)NN * 128];   // LN(x), tf32-rounded, [r][d]
__device__ float g_A [(size_t)128 * NN];   // a transposed: [d][i*768+k]
__device__ float g_B [(size_t)128 * NN];   // b transposed: [d][j*768+k]
__device__ float g_T [(size_t)128 * NN];   // t transposed: [d][i*768+j]
__device__ float g_G [(size_t)NN * 128];   // sigmoid(xn @ g_out_w), [r][e]
__device__ float g_Wc[640 * 128];          // rows 0..511: interleaved (g,p); 512..639: g_out_w
__device__ float g_Pw[128 * 128];          // p_out_w tf32

// ---------------- helpers ------------------------------------------------------
__device__ __forceinline__ float tf32r(float x) {
    unsigned u;
    asm("cvt.rna.tf32.f32 %0, %1;" : "=r"(u) : "f"(x));
    return __uint_as_float(u);
}

__device__ __forceinline__ void mma8(float c[4], const unsigned a[4], const unsigned b[2]) {
    asm volatile(
        "mma.sync.aligned.m16n8k8.row.col.f32.tf32.tf32.f32 "
        "{%0,%1,%2,%3},{%4,%5,%6,%7},{%8,%9},{%0,%1,%2,%3};"
        : "+f"(c[0]), "+f"(c[1]), "+f"(c[2]), "+f"(c[3])
        : "r"(a[0]), "r"(a[1]), "r"(a[2]), "r"(a[3]), "r"(b[0]), "r"(b[1]));
}

__device__ __forceinline__ void cpa(void* s, const void* g) {
    unsigned sa = (unsigned)__cvta_generic_to_shared(s);
    asm volatile("cp.async.cg.shared.global [%0], [%1], 16;" :: "r"(sa), "l"(g));
}
__device__ __forceinline__ void cp_commit() { asm volatile("cp.async.commit_group;"); }
template<int Nw> __device__ __forceinline__ void cp_wait() {
    asm volatile("cp.async.wait_group %0;" :: "n"(Nw));
}

// 128x128 output tile, one K-chunk of 32. sA:[128][36] (m,k)  sB:[128][36] (n,k).
__device__ __forceinline__ void gemm_c32(const float* sA, const float* sB,
                                         float acc[4][4][4],
                                         int wm, int wn, int qr, int qc) {
#pragma unroll
    for (int k = 0; k < 32; k += 8) {
        unsigned af[4][4], bf[4][2];
#pragma unroll
        for (int mt = 0; mt < 4; mt++) {
            const float* p = sA + (wm + mt * 16 + qr) * 36 + k + qc;
            af[mt][0] = __float_as_uint(p[0]);
            af[mt][1] = __float_as_uint(p[8 * 36]);
            af[mt][2] = __float_as_uint(p[4]);
            af[mt][3] = __float_as_uint(p[8 * 36 + 4]);
        }
#pragma unroll
        for (int nt = 0; nt < 4; nt++) {
            const float* p = sB + (wn + nt * 8 + qr) * 36 + k + qc;
            bf[nt][0] = __float_as_uint(p[0]);
            bf[nt][1] = __float_as_uint(p[4]);
        }
#pragma unroll
        for (int mt = 0; mt < 4; mt++)
#pragma unroll
            for (int nt = 0; nt < 4; nt++)
                mma8(acc[mt][nt], af[mt], bf[nt]);
    }
}

// ---------------- kernel 0: weight prep ----------------------------------------
__global__ void prep_w_kernel(const float* __restrict__ gin, const float* __restrict__ pin,
                              const float* __restrict__ gout, const float* __restrict__ pout) {
    int stride = gridDim.x * blockDim.x;
    for (int idx = blockIdx.x * blockDim.x + threadIdx.x; idx < 256 * 128; idx += stride) {
        int e = idx >> 7, d = idx & 127;
        g_Wc[(2 * e) * 128 + d]     = tf32r(gin[idx]);
        g_Wc[(2 * e + 1) * 128 + d] = tf32r(pin[idx]);
    }
    for (int idx = blockIdx.x * blockDim.x + threadIdx.x; idx < 128 * 128; idx += stride) {
        g_Wc[512 * 128 + idx] = tf32r(gout[idx]);
        g_Pw[idx]             = tf32r(pout[idx]);
    }
}

// ---------------- kernel 1: LayerNorm(x) -> g_xn --------------------------------
__global__ void __launch_bounds__(256) ln_in_kernel(const float* __restrict__ x,
                                                    const float* __restrict__ w,
                                                    const float* __restrict__ b) {
    int warp = threadIdx.x >> 5, lane = threadIdx.x & 31;
    size_t r = (size_t)blockIdx.x * 8 + warp;
    const float4 xv = ((const float4*)(x + r * 128))[lane];
    float s  = xv.x + xv.y + xv.z + xv.w;
    float s2 = xv.x * xv.x + xv.y * xv.y + xv.z * xv.z + xv.w * xv.w;
#pragma unroll
    for (int o = 16; o > 0; o >>= 1) {
        s  += __shfl_xor_sync(0xffffffffu, s,  o);
        s2 += __shfl_xor_sync(0xffffffffu, s2, o);
    }
    float m   = s * (1.0f / 128.0f);
    float var = s2 * (1.0f / 128.0f) - m * m;
    float inv = rsqrtf(var + 1e-5f);
    float4 wv = ((const float4*)w)[lane];
    float4 bv = ((const float4*)b)[lane];
    float4 o4;
    o4.x = tf32r((xv.x - m) * inv * wv.x + bv.x);
    o4.y = tf32r((xv.y - m) * inv * wv.y + bv.y);
    o4.z = tf32r((xv.z - m) * inv * wv.z + bv.z);
    o4.w = tf32r((xv.w - m) * inv * wv.w + bv.w);
    ((float4*)(g_xn + r * 128))[lane] = o4;
}

// ---------------- kernel 2: projections + gate + mask ---------------------------
// ntile 0..3: C = xn @ Wc (interleaved g,p) -> gated, masked, transposed into g_A/g_B.
// ntile 4   : C = xn @ g_out_w -> sigmoid -> g_G[r][e]  (row-major, no transpose).
__global__ void __launch_bounds__(256, 2) proj_kernel(const float* __restrict__ mask) {
    extern __shared__ float sm[];
    float* msk = sm + 18432;
    int ntile = blockIdx.x;
    int rt = blockIdx.y;
    int i = rt / 6, k0 = (rt % 6) * 128;
    int tid = threadIdx.x;

    if (tid < 128) msk[tid] = mask[i * 768 + k0 + tid];

    const float* Abase = g_xn + (size_t)(i * 768 + k0) * 128;
    const float* Wbase = g_Wc + (size_t)ntile * 128 * 128;

    auto ld = [&](int s, int kc) {
        float* SA = sm + s * 9216;
        float* SW = SA + 4608;
#pragma unroll
        for (int t = 0; t < 4; t++) {
            int idx = t * 256 + tid;
            int r = idx >> 3, c4 = (idx & 7) * 4;
            cpa(&SA[r * 36 + c4], &Abase[(size_t)r * 128 + kc + c4]);
            cpa(&SW[r * 36 + c4], &Wbase[(size_t)r * 128 + kc + c4]);
        }
    };

    int warp = tid >> 5, lane = tid & 31;
    int wm = (warp >> 2) * 64, wn = (warp & 3) * 32;
    int qr = lane >> 2, qc = lane & 3;
    float acc[4][4][4] = {};

    ld(0, 0);  cp_commit();
    ld(1, 32); cp_commit();
#pragma unroll 1
    for (int c = 0; c < 4; c++) {
        cp_wait<1>(); __syncthreads();
        int s = c & 1;
        gemm_c32(sm + s * 9216, sm + s * 9216 + 4608, acc, wm, wn, qr, qc);
        __syncthreads();
        int kn = (c + 2) * 32;
        if (kn < 128) ld(s, kn);
        cp_commit();
    }

    if (ntile == 4) {
        // gate: sigmoid, direct store to g_G[r][e]
#pragma unroll
        for (int mt = 0; mt < 4; mt++)
#pragma unroll
            for (int nt = 0; nt < 4; nt++) {
                int rm0 = wm + mt * 16 + qr, rm1 = rm0 + 8;
                int cn = wn + nt * 8 + qc * 2;
                size_t r0 = (size_t)(i * 768 + k0 + rm0) * 128 + cn;
                size_t r1 = (size_t)(i * 768 + k0 + rm1) * 128 + cn;
                *(float2*)&g_G[r0] = make_float2(1.0f / (1.0f + __expf(-acc[mt][nt][0])),
                                                 1.0f / (1.0f + __expf(-acc[mt][nt][1])));
                *(float2*)&g_G[r1] = make_float2(1.0f / (1.0f + __expf(-acc[mt][nt][2])),
                                                 1.0f / (1.0f + __expf(-acc[mt][nt][3])));
            }
        return;
    }

    // gate/project epilogue with transpose through smem (reuse stage buffers)
    float* stg = sm;             // [64 ch][132]
    bool isA = (ntile < 2);
#pragma unroll
    for (int mt = 0; mt < 4; mt++)
#pragma unroll
        for (int nt = 0; nt < 4; nt++) {
            int rm0 = wm + mt * 16 + qr, rm1 = rm0 + 8;
            int chl = (wn >> 1) + nt * 4 + qc;
            float v0 = acc[mt][nt][1] * (1.0f / (1.0f + __expf(-acc[mt][nt][0])));
            float v1 = acc[mt][nt][3] * (1.0f / (1.0f + __expf(-acc[mt][nt][2])));
            if (isA) { v0 *= msk[rm0]; v1 *= msk[rm1]; }
            stg[chl * 132 + rm0] = tf32r(v0);
            stg[chl * 132 + rm1] = tf32r(v1);
        }
    __syncthreads();

#pragma unroll
    for (int it = 0; it < 8; it++) {
        int idx = it * 256 + tid;
        int chl = idx >> 5, k4 = idx & 31;
        float4 v = *(float4*)&stg[chl * 132 + k4 * 4];
        int ch = ntile * 64 + chl;
        float* dst = (ch < 128) ? (g_A + (size_t)ch * NN) : (g_B + (size_t)(ch - 128) * NN);
        *(float4*)&dst[i * 768 + k0 + k4 * 4] = v;
    }
}

// ---------------- kernel 3: batched einsum  t_d = A_d @ B_d^T --------------------
__global__ void __launch_bounds__(256, 2) bgemm_kernel() {
    extern __shared__ float sm[];
    int jt = blockIdx.x, it = blockIdx.y, d = blockIdx.z;
    int tid = threadIdx.x;
    const float* Abase = g_A + (size_t)d * NN + (size_t)it * 128 * 768;
    const float* Bbase = g_B + (size_t)d * NN + (size_t)jt * 128 * 768;

    auto ld = [&](int s, int kc) {
        float* SA = sm + s * 9216;
        float* SB = SA + 4608;
#pragma unroll
        for (int t = 0; t < 4; t++) {
            int idx = t * 256 + tid;
            int r = idx >> 3, c4 = (idx & 7) * 4;
            cpa(&SA[r * 36 + c4], &Abase[(size_t)r * 768 + kc + c4]);
            cpa(&SB[r * 36 + c4], &Bbase[(size_t)r * 768 + kc + c4]);
        }
    };

    int warp = tid >> 5, lane = tid & 31;
    int wm = (warp >> 2) * 64, wn = (warp & 3) * 32;
    int qr = lane >> 2, qc = lane & 3;
    float acc[4][4][4] = {};

    ld(0, 0);  cp_commit();
    ld(1, 32); cp_commit();
#pragma unroll 1
    for (int c = 0; c < 24; c++) {
        cp_wait<1>(); __syncthreads();
        int s = c & 1;
        gemm_c32(sm + s * 9216, sm + s * 9216 + 4608, acc, wm, wn, qr, qc);
        __syncthreads();
        int kn = (c + 2) * 32;
        if (kn < 768) ld(s, kn);
        cp_commit();
    }

    float* outp = g_T + (size_t)d * NN;
#pragma unroll
    for (int mt = 0; mt < 4; mt++)
#pragma unroll
        for (int nt = 0; nt < 4; nt++) {
            int rm0 = it * 128 + wm + mt * 16 + qr;
            int cn  = jt * 128 + wn + nt * 8 + qc * 2;
            *(float2*)&outp[(size_t)rm0 * 768 + cn]       = make_float2(acc[mt][nt][0], acc[mt][nt][1]);
            *(float2*)&outp[(size_t)(rm0 + 8) * 768 + cn] = make_float2(acc[mt][nt][2], acc[mt][nt][3]);
        }
}

// ---------------- kernel 4: LN(t) over d + output projection + gate -------------
// 64-wide j tiles: sT [128 d][68], sW [128 e][132]. Gate read from g_G at epilogue.
__global__ void __launch_bounds__(256, 2) final_kernel(const float* __restrict__ now_w,
                                                       const float* __restrict__ now_b,
                                                       float* __restrict__ out) {
    extern __shared__ float sm[];
    float* sT    = sm;            // 128 x 68 = 8704
    float* sW    = sm + 8704;     // 128 x 132 = 16896
    float* meanv = sm + 25600;    // 64
    float* invv  = sm + 25664;    // 64
    float* wln   = sm + 25728;    // 128
    float* bln   = sm + 25856;    // 128
    int rt = blockIdx.x;
    int i = rt / 12, j0 = (rt % 12) * 64;
    int tid = threadIdx.x;

    if (tid < 128) { wln[tid] = now_w[tid]; bln[tid] = now_b[tid]; }

    const float* Tg = g_T + (size_t)i * 768 + j0;
#pragma unroll
    for (int t = 0; t < 8; t++) {
        int idx = t * 256 + tid;
        int dd = idx >> 4, c4 = (idx & 15) * 4;
        cpa(&sT[dd * 68 + c4], &Tg[(size_t)dd * NN + c4]);
    }
#pragma unroll
    for (int t = 0; t < 16; t++) {
        int idx = t * 256 + tid;
        int r = idx >> 5, c4 = (idx & 31) * 4;
        cpa(&sW[r * 132 + c4], &g_Pw[r * 128 + c4]);
    }
    cp_commit();
    cp_wait<0>();
    __syncthreads();

    // LN stats over d per column j (4 threads/column)
    {
        int j = tid >> 2, h = tid & 3;
        float s = 0.0f, s2 = 0.0f;
#pragma unroll 4
        for (int dd = h * 32; dd < h * 32 + 32; dd++) {
            float v = sT[dd * 68 + j];
            s += v; s2 += v * v;
        }
        s  += __shfl_xor_sync(0xffffffffu, s,  1);
        s2 += __shfl_xor_sync(0xffffffffu, s2, 1);
        s  += __shfl_xor_sync(0xffffffffu, s,  2);
        s2 += __shfl_xor_sync(0xffffffffu, s2, 2);
        if (h == 0) {
            float m   = s * (1.0f / 128.0f);
            float var = s2 * (1.0f / 128.0f) - m * m;
            meanv[j] = m;
            invv[j]  = rsqrtf(var + 1e-5f);
        }
    }
    __syncthreads();

#pragma unroll
    for (int t = 0; t < 32; t++) {
        int idx = t * 256 + tid;
        int dd = idx >> 6, j = idx & 63;
        float v = sT[dd * 68 + j];
        sT[dd * 68 + j] = tf32r((v - meanv[j]) * invv[j] * wln[dd] + bln[dd]);
    }
    __syncthreads();

    int warp = tid >> 5, lane = tid & 31;
    int wm = (warp >> 2) * 32, wn = (warp & 3) * 32;
    int qr = lane >> 2, qc = lane & 3;
    float acc[2][4][4] = {};

#pragma unroll
    for (int k = 0; k < 128; k += 8) {
        unsigned af[2][4], bf[4][2];
#pragma unroll
        for (int mt = 0; mt < 2; mt++) {
            int r = wm + mt * 16 + qr;
            const float* p0 = sT + (k + qc) * 68 + r;
            const float* p1 = sT + (k + qc + 4) * 68 + r;
            af[mt][0] = __float_as_uint(p0[0]);
            af[mt][1] = __float_as_uint(p0[8]);
            af[mt][2] = __float_as_uint(p1[0]);
            af[mt][3] = __float_as_uint(p1[8]);
        }
#pragma unroll
        for (int nt = 0; nt < 4; nt++) {
            const float* p = sW + (wn + nt * 8 + qr) * 132 + k + qc;
            bf[nt][0] = __float_as_uint(p[0]);
            bf[nt][1] = __float_as_uint(p[4]);
        }
#pragma unroll
        for (int mt = 0; mt < 2; mt++)
#pragma unroll
            for (int nt = 0; nt < 4; nt++)
                mma8(acc[mt][nt], af[mt], bf[nt]);
    }

#pragma unroll
    for (int mt = 0; mt < 2; mt++)
#pragma unroll
        for (int nt = 0; nt < 4; nt++) {
            int rj = wm + mt * 16 + qr;
            int cn = wn + nt * 8 + qc * 2;
            size_t ro0 = (size_t)(i * 768 + j0 + rj) * 128 + cn;
            size_t ro1 = ro0 + 8 * 128;
            float2 gt0 = *(const float2*)&g_G[ro0];
            float2 gt1 = *(const float2*)&g_G[ro1];
            *(float2*)&out[ro0] = make_float2(gt0.x * acc[mt][nt][0], gt0.y * acc[mt][nt][1]);
            *(float2*)&out[ro1] = make_float2(gt1.x * acc[mt][nt][2], gt1.y * acc[mt][nt][3]);
        }
}

// ---------------- launch ---------------------------------------------------------
extern "C" void kernel_launch(void* const* d_in, const int* in_sizes, int n_in,
                              void* d_out, int out_size) {
    const float* x    = (const float*)d_in[0];
    const float* mask = (const float*)d_in[1];
    const float* niw  = (const float*)d_in[2];
    const float* nib  = (const float*)d_in[3];
    const float* giw  = (const float*)d_in[4];
    const float* piw  = (const float*)d_in[5];
    const float* now  = (const float*)d_in[6];
    const float* nob  = (const float*)d_in[7];
    const float* gow  = (const float*)d_in[8];
    const float* pwo  = (const float*)d_in[9];
    float* out = (float*)d_out;

    size_t sm_proj  = 18560 * 4;   // 74240 B  (2 stages + mask)
    size_t sm_bgemm = 18432 * 4;   // 73728 B  (2 stages)
    size_t sm_final = 25984 * 4;   // 103936 B
    cudaFuncSetAttribute(proj_kernel,  cudaFuncAttributeMaxDynamicSharedMemorySize, (int)sm_proj);
    cudaFuncSetAttribute(bgemm_kernel, cudaFuncAttributeMaxDynamicSharedMemorySize, (int)sm_bgemm);
    cudaFuncSetAttribute(final_kernel, cudaFuncAttributeMaxDynamicSharedMemorySize, (int)sm_final);

    prep_w_kernel<<<64, 256>>>(giw, piw, gow, pwo);
    ln_in_kernel<<<NN / 8, 256>>>(x, niw, nib);
    proj_kernel<<<dim3(5, 4608), 256, sm_proj>>>(mask);
    bgemm_kernel<<<dim3(6, 6, 128), 256, sm_bgemm>>>();
    final_kernel<<<9216, 256, sm_final>>>(now, nob, out);
}